// round 15
// baseline (speedup 1.0000x reference)
#include <cuda_runtime.h>
#include <cuda_fp16.h>

#define NBATCH 8
#define SEQ 2048
#define DIM 128
#define NPAIR 2

// Scratch (device globals -- no allocation allowed in kernel_launch)
__device__ __half g_ph[(size_t)NPAIR * NBATCH * SEQ * DIM];        // 8 MB fp16-hi
__device__ __half g_pl[(size_t)NPAIR * NBATCH * SEQ * DIM];        // 8 MB fp16-lo
__device__ float g_att[(size_t)NPAIR * NBATCH * SEQ * SEQ];        // E=exp (full, symmetric)
__device__ float g_rpart[(size_t)NPAIR * NBATCH * 16 * SEQ];       // 2 MB Z partials
__device__ float g_cpart[(size_t)NPAIR * NBATCH * 16 * SEQ];       // 2 MB colsum partials
__device__ float g_dexp[NPAIR * NBATCH * SEQ];                     // diagonal exp
__device__ float g_rinv[NPAIR * NBATCH * SEQ];
__device__ float g_diag[NPAIR * NBATCH * SEQ];                     // diag softmax value
__device__ float g_score[NPAIR * NBATCH * SEQ];
__device__ float g_theta[NPAIR * NBATCH];

// m16n8k16 fp16 MMA, fp32 accum (baseline PTX since sm_75; no 103a feature)
__device__ __forceinline__ void mma_f16(float d[4], const unsigned a[4],
                                        const unsigned b[2]) {
    asm volatile(
        "mma.sync.aligned.m16n8k16.row.col.f32.f16.f16.f32 "
        "{%0,%1,%2,%3}, {%4,%5,%6,%7}, {%8,%9}, {%0,%1,%2,%3};"
        : "+f"(d[0]), "+f"(d[1]), "+f"(d[2]), "+f"(d[3])
        : "r"(a[0]), "r"(a[1]), "r"(a[2]), "r"(a[3]), "r"(b[0]), "r"(b[1]));
}

// Upper-tri tile index -> (ti, tj)
__device__ __forceinline__ void tile_coords(int t, int& ti, int& tj) {
    ti = 0;
    while (t >= 16 - ti) { t -= 16 - ti; ti++; }
    tj = ti + t;
}

// ---------------------------------------------------------------------------
// Projection: P = X @ W^T + b (exact fp32 FMA), then split into fp16 hi/lo.
// 64-row tiles for occupancy: grid (256, 2), block 256 (3.5 CTAs/SM).
// Per-output fmaf chain identical to the 128-row version (bit-identical P).
// ---------------------------------------------------------------------------
__global__ __launch_bounds__(256) void proj_kernel(
    const float* __restrict__ xt, const float* __restrict__ xf,
    const float* __restrict__ W, const float* __restrict__ bias)
{
    __shared__ float As[64][33];
    __shared__ float Bs[128][33];
    const int p = blockIdx.y;
    const float* __restrict__ X = (p == 0) ? xt : xf;
    const int rbase = blockIdx.x * 64;
    const int tid = threadIdx.x;
    const int tx = tid & 15, ty = tid >> 4;
    const int r0 = ty * 4, c0 = tx * 8;
    float acc[4][8];
#pragma unroll
    for (int i = 0; i < 4; i++)
#pragma unroll
        for (int j = 0; j < 8; j++) acc[i][j] = 0.f;

    for (int kk0 = 0; kk0 < DIM; kk0 += 32) {
#pragma unroll
        for (int it = 0; it < 2; it++) {           // A: 64 rows x 32 k
            int idx4 = it * 256 + tid;
            int r = idx4 >> 3;
            int k4 = (idx4 & 7) * 4;
            float4 v = *(const float4*)(X + (size_t)(rbase + r) * DIM + kk0 + k4);
            As[r][k4 + 0] = v.x; As[r][k4 + 1] = v.y; As[r][k4 + 2] = v.z; As[r][k4 + 3] = v.w;
        }
#pragma unroll
        for (int it = 0; it < 4; it++) {           // B: 128 rows x 32 k
            int idx4 = it * 256 + tid;
            int r = idx4 >> 3;
            int k4 = (idx4 & 7) * 4;
            float4 w = *(const float4*)(W + (size_t)r * DIM + kk0 + k4);
            Bs[r][k4 + 0] = w.x; Bs[r][k4 + 1] = w.y; Bs[r][k4 + 2] = w.z; Bs[r][k4 + 3] = w.w;
        }
        __syncthreads();
#pragma unroll
        for (int k = 0; k < 32; k++) {
            float a[4], b[8];
#pragma unroll
            for (int j = 0; j < 8; j++) b[j] = Bs[c0 + j][k];
#pragma unroll
            for (int i = 0; i < 4; i++) a[i] = As[r0 + i][k];
#pragma unroll
            for (int i = 0; i < 4; i++)
#pragma unroll
                for (int j = 0; j < 8; j++)
                    acc[i][j] = fmaf(a[i], b[j], acc[i][j]);
        }
        __syncthreads();
    }
    float bv[8];
#pragma unroll
    for (int j = 0; j < 8; j++) bv[j] = bias[c0 + j];
    const size_t obase = ((size_t)p * NBATCH * SEQ + rbase) * DIM;
#pragma unroll
    for (int i = 0; i < 4; i++) {
        __half h[8], l[8];
#pragma unroll
        for (int j = 0; j < 8; j++) {
            float v = acc[i][j] + bv[j];
            h[j] = __float2half_rn(v);
            l[j] = __float2half_rn(v - __half2float(h[j]));
        }
        __half* dh = g_ph + obase + (size_t)(r0 + i) * DIM + c0;
        __half* dl = g_pl + obase + (size_t)(r0 + i) * DIM + c0;
#pragma unroll
        for (int j = 0; j < 4; j++) {
            ((__half2*)dh)[j] = __halves2half2(h[2 * j], h[2 * j + 1]);
            ((__half2*)dl)[j] = __halves2half2(l[2 * j], l[2 * j + 1]);
        }
    }
}

// ---------------------------------------------------------------------------
// Attention: E = exp(scale * P P^T) via mma.sync fp16 3x-split
// (hi*hi + hi*lo + lo*hi; dropped lo*lo -- proven margin).
// R10 mainloop EXACTLY (scalar LDS, 3 separate passes, synchronous fills).
// Symmetric: upper-tri tiles computed, BOTH halves stored (R9-stable pattern).
// grid (136, 8, 2), block 256. 8 warps x (32x64) fragments.
// Smem tiles: rows of 16 half2 padded to 20 -> conflict-free fragment loads.
// ---------------------------------------------------------------------------
#define HROW 20                       // half2 (=uint) per row, padded
#define HT_SZ (128 * HROW)            // uints per staged tensor chunk

struct Frag { float v[2][8][4]; };

__device__ __forceinline__ void mac16(const unsigned* __restrict__ A,
                                      const unsigned* __restrict__ B,
                                      Frag& f, int wr, int wc, int lq, int lr)
{
#pragma unroll
    for (int s = 0; s < 2; s++) {          // two k16 steps per 32-k chunk
        const int kb = s * 8;
        unsigned a[2][4], b[8][2];
#pragma unroll
        for (int mt = 0; mt < 2; mt++) {
            const int m = wr * 32 + mt * 16;
            a[mt][0] = A[(m + lq) * HROW + kb + lr];
            a[mt][1] = A[(m + 8 + lq) * HROW + kb + lr];
            a[mt][2] = A[(m + lq) * HROW + kb + 4 + lr];
            a[mt][3] = A[(m + 8 + lq) * HROW + kb + 4 + lr];
        }
#pragma unroll
        for (int nt = 0; nt < 8; nt++) {
            const int n = wc * 64 + nt * 8 + lq;
            b[nt][0] = B[n * HROW + kb + lr];
            b[nt][1] = B[n * HROW + kb + 4 + lr];
        }
#pragma unroll
        for (int mt = 0; mt < 2; mt++)
#pragma unroll
            for (int nt = 0; nt < 8; nt++)
                mma_f16(f.v[mt][nt], a[mt], b[nt]);
    }
}

__global__ __launch_bounds__(256) void att_kernel()
{
    __shared__ unsigned sAh[HT_SZ], sAl[HT_SZ], sBh[HT_SZ], sBl[HT_SZ];

    int ti, tj;
    tile_coords(blockIdx.x, ti, tj);
    const int pn = blockIdx.z * NBATCH + blockIdx.y;
    const size_t pbase = (size_t)pn * SEQ * DIM;
    const __half* __restrict__ Ah = g_ph + pbase + (size_t)ti * 128 * DIM;
    const __half* __restrict__ Al = g_pl + pbase + (size_t)ti * 128 * DIM;
    const __half* __restrict__ Bh = g_ph + pbase + (size_t)tj * 128 * DIM;
    const __half* __restrict__ Bl = g_pl + pbase + (size_t)tj * 128 * DIM;
    float* __restrict__ att = g_att + (size_t)pn * SEQ * SEQ;

    const int tid = threadIdx.x;
    const int wid = tid >> 5, lane = tid & 31;
    const int lq = lane >> 2, lr = lane & 3;
    const int wr = wid & 3, wc = wid >> 2;

    Frag f;
#pragma unroll
    for (int mt = 0; mt < 2; mt++)
#pragma unroll
        for (int nt = 0; nt < 8; nt++)
#pragma unroll
            for (int e = 0; e < 4; e++) f.v[mt][nt][e] = 0.f;

    const int fr = tid >> 1;          // fill row 0..127
    const int fh = tid & 1;           // which 16-half half of the 32-half chunk
    for (int c = 0; c < 4; c++) {
        const int kk0 = c * 32;
        const size_t goff = (size_t)fr * DIM + kk0 + fh * 16;
        const unsigned so = fr * HROW + fh * 8;
        *(uint4*)&sAh[so]     = *(const uint4*)(Ah + goff);
        *(uint4*)&sAh[so + 4] = *(const uint4*)(Ah + goff + 8);
        *(uint4*)&sAl[so]     = *(const uint4*)(Al + goff);
        *(uint4*)&sAl[so + 4] = *(const uint4*)(Al + goff + 8);
        *(uint4*)&sBh[so]     = *(const uint4*)(Bh + goff);
        *(uint4*)&sBh[so + 4] = *(const uint4*)(Bh + goff + 8);
        *(uint4*)&sBl[so]     = *(const uint4*)(Bl + goff);
        *(uint4*)&sBl[so + 4] = *(const uint4*)(Bl + goff + 8);
        __syncthreads();
        mac16(sAh, sBh, f, wr, wc, lq, lr);   // hi*hi
        mac16(sAh, sBl, f, wr, wc, lq, lr);   // hi*lo
        mac16(sAl, sBh, f, wr, wc, lq, lr);   // lo*hi
        __syncthreads();
    }

    // ---- epilogue: E = exp(scale*a), stores + deterministic partial sums ---
    const float scale = 0.088388347648318447f;  // 1/sqrt(128)
    float rp[4] = {0.f, 0.f, 0.f, 0.f};        // row partials (this thread's 4 rows)
    float cp0[8], cp1[8];                       // col partials (even/odd col per nt)
#pragma unroll
    for (int nt = 0; nt < 8; nt++) { cp0[nt] = 0.f; cp1[nt] = 0.f; }

#pragma unroll
    for (int mt = 0; mt < 2; mt++) {
#pragma unroll
        for (int nt = 0; nt < 8; nt++) {
            const int rl = wr * 32 + mt * 16 + lq;          // local row
            const int cl = wc * 64 + nt * 8 + 2 * lr;       // local col
            const float e0 = expf(f.v[mt][nt][0] * scale);
            const float e1 = expf(f.v[mt][nt][1] * scale);
            const float e2 = expf(f.v[mt][nt][2] * scale);
            const float e3 = expf(f.v[mt][nt][3] * scale);
            *(float2*)&att[(size_t)(ti * 128 + rl) * SEQ + tj * 128 + cl] =
                make_float2(e0, e1);
            *(float2*)&att[(size_t)(ti * 128 + rl + 8) * SEQ + tj * 128 + cl] =
                make_float2(e2, e3);
            if (ti != tj) {
                att[(size_t)(tj * 128 + cl) * SEQ + ti * 128 + rl] = e0;
                att[(size_t)(tj * 128 + cl + 1) * SEQ + ti * 128 + rl] = e1;
                att[(size_t)(tj * 128 + cl) * SEQ + ti * 128 + rl + 8] = e2;
                att[(size_t)(tj * 128 + cl + 1) * SEQ + ti * 128 + rl + 8] = e3;
            } else {
                // diagonal exp values
                if (rl == cl)         g_dexp[pn * SEQ + ti * 128 + rl] = e0;
                if (rl == cl + 1)     g_dexp[pn * SEQ + ti * 128 + rl] = e1;
                if (rl + 8 == cl)     g_dexp[pn * SEQ + ti * 128 + rl + 8] = e2;
                if (rl + 8 == cl + 1) g_dexp[pn * SEQ + ti * 128 + rl + 8] = e3;
            }
            rp[mt * 2 + 0] += e0 + e1;
            rp[mt * 2 + 1] += e2 + e3;
            cp0[nt] += e0 + e2;
            cp1[nt] += e1 + e3;
        }
    }

    // row partials: reduce over lr (4 lanes hold different columns, same row)
#pragma unroll
    for (int i = 0; i < 4; i++) {
        rp[i] += __shfl_xor_sync(0xffffffffu, rp[i], 1);
        rp[i] += __shfl_xor_sync(0xffffffffu, rp[i], 2);
    }
    // col partials: reduce over lq (8 lanes hold different rows, same col)
#pragma unroll
    for (int nt = 0; nt < 8; nt++) {
        cp0[nt] += __shfl_xor_sync(0xffffffffu, cp0[nt], 4);
        cp0[nt] += __shfl_xor_sync(0xffffffffu, cp0[nt], 8);
        cp0[nt] += __shfl_xor_sync(0xffffffffu, cp0[nt], 16);
        cp1[nt] += __shfl_xor_sync(0xffffffffu, cp1[nt], 4);
        cp1[nt] += __shfl_xor_sync(0xffffffffu, cp1[nt], 8);
        cp1[nt] += __shfl_xor_sync(0xffffffffu, cp1[nt], 16);
    }

    float* s_row = (float*)sAh;          // [128][2]   (tile smem reuse)
    float* s_col = (float*)sAh + 256;    // [128][4]
    if (lr == 0) {
#pragma unroll
        for (int i = 0; i < 4; i++) {
            int row = wr * 32 + (i >> 1) * 16 + (i & 1) * 8 + lq;
            s_row[row * 2 + wc] = rp[i];
        }
    }
    if (lq == 0) {
#pragma unroll
        for (int nt = 0; nt < 8; nt++) {
            int col = wc * 64 + nt * 8 + 2 * lr;
            s_col[col * 4 + wr] = cp0[nt];
            s_col[(col + 1) * 4 + wr] = cp1[nt];
        }
    }
    __syncthreads();
    if (tid < 128) {
        float z = s_row[tid * 2] + s_row[tid * 2 + 1];
        g_rpart[((size_t)pn * 16 + tj) * SEQ + ti * 128 + tid] = z;
    } else if (ti != tj) {
        int cc = tid - 128;
        float z = s_col[cc * 4] + s_col[cc * 4 + 1] + s_col[cc * 4 + 2] + s_col[cc * 4 + 3];
        g_rpart[((size_t)pn * 16 + ti) * SEQ + tj * 128 + cc] = z;
    }
}

// ---------------------------------------------------------------------------
// Z-reduction: rinv = 1/(sum of 16 tile partials, fixed order);
// diag softmax value = dexp * rinv. grid 128, block 256.
// ---------------------------------------------------------------------------
__global__ __launch_bounds__(256) void zred_kernel()
{
    const int rid = blockIdx.x * 256 + threadIdx.x;   // 0 .. 32767
    const int pn = rid >> 11;
    const int l = rid & (SEQ - 1);
    float z = 0.f;
#pragma unroll
    for (int s = 0; s < 16; s++)
        z += g_rpart[((size_t)pn * 16 + s) * SEQ + l];
    const float inv = 1.f / z;
    g_rinv[rid] = inv;
    g_diag[rid] = g_dexp[rid] * inv;
}

// ---------------------------------------------------------------------------
// Column sums via symmetric tiles: one read of upper tile T(ti,tj) yields
//   A[c] = sum_r T[r,c]*rinv[ti*128+r]  -> cpart slot ti, block tj
//   B[r] = sum_c T[r,c]*rinv[tj*128+c]  -> cpart slot tj, block ti (ti!=tj)
// grid (136, 8, 2), block 256 (8 warps x 16 rows; lane owns 4 cols).
// Loads batched 8 rows ahead (MLP 8) -- arithmetic order identical to R10.
// ---------------------------------------------------------------------------
__global__ __launch_bounds__(256) void colsum_kernel()
{
    __shared__ float srow[128], scol[128], rowout[128];
    __shared__ float colacc[8][132];

    int ti, tj;
    tile_coords(blockIdx.x, ti, tj);
    const int pn = blockIdx.z * NBATCH + blockIdx.y;
    const float* __restrict__ att = g_att + (size_t)pn * SEQ * SEQ;
    const float* __restrict__ rinv = g_rinv + pn * SEQ;
    const int tid = threadIdx.x;
    const int wid = tid >> 5, lane = tid & 31;

    if (tid < 128) srow[tid] = rinv[ti * 128 + tid];
    else           scol[tid - 128] = rinv[tj * 128 + (tid - 128)];
    __syncthreads();

    const float rv0 = scol[lane * 4 + 0];
    const float rv1 = scol[lane * 4 + 1];
    const float rv2 = scol[lane * 4 + 2];
    const float rv3 = scol[lane * 4 + 3];
    float ca0 = 0.f, ca1 = 0.f, ca2 = 0.f, ca3 = 0.f;

#pragma unroll
    for (int grp = 0; grp < 2; grp++) {
        float4 v[8];
#pragma unroll
        for (int rr = 0; rr < 8; rr++) {
            const int r = wid * 16 + grp * 8 + rr;
            v[rr] = *(const float4*)&att[(size_t)(ti * 128 + r) * SEQ + tj * 128 + lane * 4];
        }
#pragma unroll
        for (int rr = 0; rr < 8; rr++) {
            const int r = wid * 16 + grp * 8 + rr;
            const float w = srow[r];
            ca0 = fmaf(v[rr].x, w, ca0);
            ca1 = fmaf(v[rr].y, w, ca1);
            ca2 = fmaf(v[rr].z, w, ca2);
            ca3 = fmaf(v[rr].w, w, ca3);
            float rs = v[rr].x * rv0 + v[rr].y * rv1 + v[rr].z * rv2 + v[rr].w * rv3;
            rs += __shfl_xor_sync(0xffffffffu, rs, 1);
            rs += __shfl_xor_sync(0xffffffffu, rs, 2);
            rs += __shfl_xor_sync(0xffffffffu, rs, 4);
            rs += __shfl_xor_sync(0xffffffffu, rs, 8);
            rs += __shfl_xor_sync(0xffffffffu, rs, 16);
            if (lane == 0) rowout[r] = rs;
        }
    }
    colacc[wid][lane * 4 + 0] = ca0;
    colacc[wid][lane * 4 + 1] = ca1;
    colacc[wid][lane * 4 + 2] = ca2;
    colacc[wid][lane * 4 + 3] = ca3;
    __syncthreads();

    if (tid < 128) {
        float a = 0.f;
#pragma unroll
        for (int w = 0; w < 8; w++) a += colacc[w][tid];
        g_cpart[((size_t)pn * 16 + ti) * SEQ + tj * 128 + tid] = a;
    } else if (ti != tj) {
        const int r = tid - 128;
        g_cpart[((size_t)pn * 16 + tj) * SEQ + ti * 128 + r] = rowout[r];
    }
}

// ---------------------------------------------------------------------------
// Per (pair,batch): final score (16 fixed-order slots minus diagonal),
// bitonic sort, theta = 1024-th smallest.
// ---------------------------------------------------------------------------
__global__ __launch_bounds__(1024) void select_kernel()
{
    const int pn = blockIdx.x;
    __shared__ float s[2048];
    const int tid = threadIdx.x;
    for (int i = tid; i < SEQ; i += 1024) {
        float v = 0.f;
#pragma unroll
        for (int c = 0; c < 16; c++)
            v += g_cpart[((size_t)pn * 16 + c) * SEQ + i];
        v -= g_diag[pn * SEQ + i];
        g_score[pn * SEQ + i] = v;
        s[i] = v;
    }
    __syncthreads();
    for (int k = 2; k <= 2048; k <<= 1) {
        for (int j = k >> 1; j > 0; j >>= 1) {
            for (int idx = tid; idx < 2048; idx += 1024) {
                int ixj = idx ^ j;
                if (ixj > idx) {
                    bool up = ((idx & k) == 0);
                    float a = s[idx], b = s[ixj];
                    if ((a > b) == up) { s[idx] = b; s[ixj] = a; }
                }
            }
            __syncthreads();
        }
    }
    if (tid == 0) g_theta[pn] = s[1023];   // 1024-th smallest
}

// ---------------------------------------------------------------------------
// Output blend.
// ---------------------------------------------------------------------------
__global__ __launch_bounds__(256) void output_kernel(
    const float* __restrict__ xt, const float* __restrict__ xf, float* __restrict__ out)
{
    const int idx = blockIdx.x * 256 + threadIdx.x;
    const int nl = idx >> 5;
    const int n = nl >> 11;
    const int l = nl & (SEQ - 1);
    const float st = g_score[n * SEQ + l];
    const float sf = g_score[(NBATCH + n) * SEQ + l];
    const bool mt = st <= g_theta[n];
    const bool mf = sf <= g_theta[NBATCH + n];
    const bool mt1 = mt && !mf;
    const bool mf1 = mf && !mt;
    const float4 vt = ((const float4*)xt)[idx];
    const float4 vf = ((const float4*)xf)[idx];
    float4 avg;
    avg.x = 0.5f * (vt.x + vf.x);
    avg.y = 0.5f * (vt.y + vf.y);
    avg.z = 0.5f * (vt.z + vf.z);
    avg.w = 0.5f * (vt.w + vf.w);
    ((float4*)out)[idx] = mt1 ? avg : vt;
    ((float4*)out)[(size_t)NBATCH * SEQ * (DIM / 4) + idx] = mf1 ? avg : vf;
}

extern "C" void kernel_launch(void* const* d_in, const int* in_sizes, int n_in,
                              void* d_out, int out_size)
{
    const float* xt = (const float*)d_in[0];
    const float* xf = (const float*)d_in[1];
    const float* W  = (const float*)d_in[2];
    const float* b  = (const float*)d_in[3];
    float* out = (float*)d_out;

    proj_kernel<<<dim3(256, 2), 256>>>(xt, xf, W, b);
    att_kernel<<<dim3(136, 8, 2), 256>>>();
    zred_kernel<<<128, 256>>>();
    colsum_kernel<<<dim3(136, 8, 2), 256>>>();
    select_kernel<<<16, 1024>>>();
    output_kernel<<<2048, 256>>>(xt, xf, out);
}

// round 16
// speedup vs baseline: 1.0353x; 1.0353x over previous
#include <cuda_runtime.h>
#include <cuda_fp16.h>

#define NBATCH 8
#define SEQ 2048
#define DIM 128
#define NPAIR 2

// Scratch (device globals -- no allocation allowed in kernel_launch)
__device__ __half g_ph[(size_t)NPAIR * NBATCH * SEQ * DIM];        // 8 MB fp16-hi
__device__ __half g_pl[(size_t)NPAIR * NBATCH * SEQ * DIM];        // 8 MB fp16-lo
__device__ float g_att[(size_t)NPAIR * NBATCH * SEQ * SEQ];        // E=exp (full, symmetric)
__device__ float g_rpart[(size_t)NPAIR * NBATCH * 16 * SEQ];       // 2 MB Z partials
__device__ float g_cpart[(size_t)NPAIR * NBATCH * 16 * SEQ];       // 2 MB colsum partials
__device__ float g_dexp[NPAIR * NBATCH * SEQ];                     // diagonal exp
__device__ float g_rinv[NPAIR * NBATCH * SEQ];
__device__ float g_diag[NPAIR * NBATCH * SEQ];                     // diag softmax value
__device__ float g_score[NPAIR * NBATCH * SEQ];
__device__ float g_theta[NPAIR * NBATCH];

// m16n8k16 fp16 MMA, fp32 accum (baseline PTX since sm_75; no 103a feature)
__device__ __forceinline__ void mma_f16(float d[4], const unsigned a[4],
                                        const unsigned b[2]) {
    asm volatile(
        "mma.sync.aligned.m16n8k16.row.col.f32.f16.f16.f32 "
        "{%0,%1,%2,%3}, {%4,%5,%6,%7}, {%8,%9}, {%0,%1,%2,%3};"
        : "+f"(d[0]), "+f"(d[1]), "+f"(d[2]), "+f"(d[3])
        : "r"(a[0]), "r"(a[1]), "r"(a[2]), "r"(a[3]), "r"(b[0]), "r"(b[1]));
}

// Upper-tri tile index -> (ti, tj)
__device__ __forceinline__ void tile_coords(int t, int& ti, int& tj) {
    ti = 0;
    while (t >= 16 - ti) { t -= 16 - ti; ti++; }
    tj = ti + t;
}

// ---------------------------------------------------------------------------
// Projection: P = X @ W^T + b (exact fp32 FMA), then split into fp16 hi/lo.
// R10 version: grid (128, 2), block 256, 128-row tiles.
// ---------------------------------------------------------------------------
__global__ __launch_bounds__(256) void proj_kernel(
    const float* __restrict__ xt, const float* __restrict__ xf,
    const float* __restrict__ W, const float* __restrict__ bias)
{
    __shared__ float As[128][33];
    __shared__ float Bs[128][33];
    const int p = blockIdx.y;
    const float* __restrict__ X = (p == 0) ? xt : xf;
    const int rbase = blockIdx.x * 128;
    const int tid = threadIdx.x;
    const int tx = tid & 15, ty = tid >> 4;
    const int r0 = ty * 8, c0 = tx * 8;
    float acc[8][8];
#pragma unroll
    for (int i = 0; i < 8; i++)
#pragma unroll
        for (int j = 0; j < 8; j++) acc[i][j] = 0.f;

    for (int kk0 = 0; kk0 < DIM; kk0 += 32) {
#pragma unroll
        for (int it = 0; it < 4; it++) {
            int idx4 = it * 256 + tid;
            int r = idx4 >> 3;
            int k4 = (idx4 & 7) * 4;
            float4 v = *(const float4*)(X + (size_t)(rbase + r) * DIM + kk0 + k4);
            As[r][k4 + 0] = v.x; As[r][k4 + 1] = v.y; As[r][k4 + 2] = v.z; As[r][k4 + 3] = v.w;
            float4 w = *(const float4*)(W + (size_t)r * DIM + kk0 + k4);
            Bs[r][k4 + 0] = w.x; Bs[r][k4 + 1] = w.y; Bs[r][k4 + 2] = w.z; Bs[r][k4 + 3] = w.w;
        }
        __syncthreads();
#pragma unroll
        for (int k = 0; k < 32; k++) {
            float a[8], b[8];
#pragma unroll
            for (int j = 0; j < 8; j++) { a[j] = As[r0 + j][k]; b[j] = Bs[c0 + j][k]; }
#pragma unroll
            for (int i = 0; i < 8; i++)
#pragma unroll
                for (int j = 0; j < 8; j++)
                    acc[i][j] = fmaf(a[i], b[j], acc[i][j]);
        }
        __syncthreads();
    }
    float bv[8];
#pragma unroll
    for (int j = 0; j < 8; j++) bv[j] = bias[c0 + j];
    const size_t obase = ((size_t)p * NBATCH * SEQ + rbase) * DIM;
#pragma unroll
    for (int i = 0; i < 8; i++) {
        __half h[8], l[8];
#pragma unroll
        for (int j = 0; j < 8; j++) {
            float v = acc[i][j] + bv[j];
            h[j] = __float2half_rn(v);
            l[j] = __float2half_rn(v - __half2float(h[j]));
        }
        __half* dh = g_ph + obase + (size_t)(r0 + i) * DIM + c0;
        __half* dl = g_pl + obase + (size_t)(r0 + i) * DIM + c0;
#pragma unroll
        for (int j = 0; j < 4; j++) {
            ((__half2*)dh)[j] = __halves2half2(h[2 * j], h[2 * j + 1]);
            ((__half2*)dl)[j] = __halves2half2(l[2 * j], l[2 * j + 1]);
        }
    }
}

// ---------------------------------------------------------------------------
// Attention: E = exp(scale * P P^T) via mma.sync fp16 3x-split
// (hi*hi + hi*lo + lo*hi; dropped lo*lo -- proven margin).
// R10 mainloop EXACTLY (scalar LDS, 3 separate passes, synchronous fills).
// Symmetric: upper-tri tiles computed, BOTH halves stored (R9-stable pattern).
// grid (136, 8, 2), block 256. 8 warps x (32x64) fragments.
// Smem tiles: rows of 16 half2 padded to 20 -> conflict-free fragment loads.
// ---------------------------------------------------------------------------
#define HROW 20                       // half2 (=uint) per row, padded
#define HT_SZ (128 * HROW)            // uints per staged tensor chunk

struct Frag { float v[2][8][4]; };

__device__ __forceinline__ void mac16(const unsigned* __restrict__ A,
                                      const unsigned* __restrict__ B,
                                      Frag& f, int wr, int wc, int lq, int lr)
{
#pragma unroll
    for (int s = 0; s < 2; s++) {          // two k16 steps per 32-k chunk
        const int kb = s * 8;
        unsigned a[2][4], b[8][2];
#pragma unroll
        for (int mt = 0; mt < 2; mt++) {
            const int m = wr * 32 + mt * 16;
            a[mt][0] = A[(m + lq) * HROW + kb + lr];
            a[mt][1] = A[(m + 8 + lq) * HROW + kb + lr];
            a[mt][2] = A[(m + lq) * HROW + kb + 4 + lr];
            a[mt][3] = A[(m + 8 + lq) * HROW + kb + 4 + lr];
        }
#pragma unroll
        for (int nt = 0; nt < 8; nt++) {
            const int n = wc * 64 + nt * 8 + lq;
            b[nt][0] = B[n * HROW + kb + lr];
            b[nt][1] = B[n * HROW + kb + 4 + lr];
        }
#pragma unroll
        for (int mt = 0; mt < 2; mt++)
#pragma unroll
            for (int nt = 0; nt < 8; nt++)
                mma_f16(f.v[mt][nt], a[mt], b[nt]);
    }
}

__global__ __launch_bounds__(256) void att_kernel()
{
    __shared__ unsigned sAh[HT_SZ], sAl[HT_SZ], sBh[HT_SZ], sBl[HT_SZ];

    int ti, tj;
    tile_coords(blockIdx.x, ti, tj);
    const int pn = blockIdx.z * NBATCH + blockIdx.y;
    const size_t pbase = (size_t)pn * SEQ * DIM;
    const __half* __restrict__ Ah = g_ph + pbase + (size_t)ti * 128 * DIM;
    const __half* __restrict__ Al = g_pl + pbase + (size_t)ti * 128 * DIM;
    const __half* __restrict__ Bh = g_ph + pbase + (size_t)tj * 128 * DIM;
    const __half* __restrict__ Bl = g_pl + pbase + (size_t)tj * 128 * DIM;
    float* __restrict__ att = g_att + (size_t)pn * SEQ * SEQ;

    const int tid = threadIdx.x;
    const int wid = tid >> 5, lane = tid & 31;
    const int lq = lane >> 2, lr = lane & 3;
    const int wr = wid & 3, wc = wid >> 2;

    Frag f;
#pragma unroll
    for (int mt = 0; mt < 2; mt++)
#pragma unroll
        for (int nt = 0; nt < 8; nt++)
#pragma unroll
            for (int e = 0; e < 4; e++) f.v[mt][nt][e] = 0.f;

    const int fr = tid >> 1;          // fill row 0..127
    const int fh = tid & 1;           // which 16-half half of the 32-half chunk
    for (int c = 0; c < 4; c++) {
        const int kk0 = c * 32;
        const size_t goff = (size_t)fr * DIM + kk0 + fh * 16;
        const unsigned so = fr * HROW + fh * 8;
        *(uint4*)&sAh[so]     = *(const uint4*)(Ah + goff);
        *(uint4*)&sAh[so + 4] = *(const uint4*)(Ah + goff + 8);
        *(uint4*)&sAl[so]     = *(const uint4*)(Al + goff);
        *(uint4*)&sAl[so + 4] = *(const uint4*)(Al + goff + 8);
        *(uint4*)&sBh[so]     = *(const uint4*)(Bh + goff);
        *(uint4*)&sBh[so + 4] = *(const uint4*)(Bh + goff + 8);
        *(uint4*)&sBl[so]     = *(const uint4*)(Bl + goff);
        *(uint4*)&sBl[so + 4] = *(const uint4*)(Bl + goff + 8);
        __syncthreads();
        mac16(sAh, sBh, f, wr, wc, lq, lr);   // hi*hi
        mac16(sAh, sBl, f, wr, wc, lq, lr);   // hi*lo
        mac16(sAl, sBh, f, wr, wc, lq, lr);   // lo*hi
        __syncthreads();
    }

    // ---- epilogue: E = exp(scale*a), stores + deterministic partial sums ---
    const float scale = 0.088388347648318447f;  // 1/sqrt(128)
    float rp[4] = {0.f, 0.f, 0.f, 0.f};        // row partials (this thread's 4 rows)
    float cp0[8], cp1[8];                       // col partials (even/odd col per nt)
#pragma unroll
    for (int nt = 0; nt < 8; nt++) { cp0[nt] = 0.f; cp1[nt] = 0.f; }

#pragma unroll
    for (int mt = 0; mt < 2; mt++) {
#pragma unroll
        for (int nt = 0; nt < 8; nt++) {
            const int rl = wr * 32 + mt * 16 + lq;          // local row
            const int cl = wc * 64 + nt * 8 + 2 * lr;       // local col
            const float e0 = expf(f.v[mt][nt][0] * scale);
            const float e1 = expf(f.v[mt][nt][1] * scale);
            const float e2 = expf(f.v[mt][nt][2] * scale);
            const float e3 = expf(f.v[mt][nt][3] * scale);
            *(float2*)&att[(size_t)(ti * 128 + rl) * SEQ + tj * 128 + cl] =
                make_float2(e0, e1);
            *(float2*)&att[(size_t)(ti * 128 + rl + 8) * SEQ + tj * 128 + cl] =
                make_float2(e2, e3);
            if (ti != tj) {
                att[(size_t)(tj * 128 + cl) * SEQ + ti * 128 + rl] = e0;
                att[(size_t)(tj * 128 + cl + 1) * SEQ + ti * 128 + rl] = e1;
                att[(size_t)(tj * 128 + cl) * SEQ + ti * 128 + rl + 8] = e2;
                att[(size_t)(tj * 128 + cl + 1) * SEQ + ti * 128 + rl + 8] = e3;
            } else {
                // diagonal exp values
                if (rl == cl)         g_dexp[pn * SEQ + ti * 128 + rl] = e0;
                if (rl == cl + 1)     g_dexp[pn * SEQ + ti * 128 + rl] = e1;
                if (rl + 8 == cl)     g_dexp[pn * SEQ + ti * 128 + rl + 8] = e2;
                if (rl + 8 == cl + 1) g_dexp[pn * SEQ + ti * 128 + rl + 8] = e3;
            }
            rp[mt * 2 + 0] += e0 + e1;
            rp[mt * 2 + 1] += e2 + e3;
            cp0[nt] += e0 + e2;
            cp1[nt] += e1 + e3;
        }
    }

    // row partials: reduce over lr (4 lanes hold different columns, same row)
#pragma unroll
    for (int i = 0; i < 4; i++) {
        rp[i] += __shfl_xor_sync(0xffffffffu, rp[i], 1);
        rp[i] += __shfl_xor_sync(0xffffffffu, rp[i], 2);
    }
    // col partials: reduce over lq (8 lanes hold different rows, same col)
#pragma unroll
    for (int nt = 0; nt < 8; nt++) {
        cp0[nt] += __shfl_xor_sync(0xffffffffu, cp0[nt], 4);
        cp0[nt] += __shfl_xor_sync(0xffffffffu, cp0[nt], 8);
        cp0[nt] += __shfl_xor_sync(0xffffffffu, cp0[nt], 16);
        cp1[nt] += __shfl_xor_sync(0xffffffffu, cp1[nt], 4);
        cp1[nt] += __shfl_xor_sync(0xffffffffu, cp1[nt], 8);
        cp1[nt] += __shfl_xor_sync(0xffffffffu, cp1[nt], 16);
    }

    float* s_row = (float*)sAh;          // [128][2]   (tile smem reuse)
    float* s_col = (float*)sAh + 256;    // [128][4]
    if (lr == 0) {
#pragma unroll
        for (int i = 0; i < 4; i++) {
            int row = wr * 32 + (i >> 1) * 16 + (i & 1) * 8 + lq;
            s_row[row * 2 + wc] = rp[i];
        }
    }
    if (lq == 0) {
#pragma unroll
        for (int nt = 0; nt < 8; nt++) {
            int col = wc * 64 + nt * 8 + 2 * lr;
            s_col[col * 4 + wr] = cp0[nt];
            s_col[(col + 1) * 4 + wr] = cp1[nt];
        }
    }
    __syncthreads();
    if (tid < 128) {
        float z = s_row[tid * 2] + s_row[tid * 2 + 1];
        g_rpart[((size_t)pn * 16 + tj) * SEQ + ti * 128 + tid] = z;
    } else if (ti != tj) {
        int cc = tid - 128;
        float z = s_col[cc * 4] + s_col[cc * 4 + 1] + s_col[cc * 4 + 2] + s_col[cc * 4 + 3];
        g_rpart[((size_t)pn * 16 + ti) * SEQ + tj * 128 + cc] = z;
    }
}

// ---------------------------------------------------------------------------
// Z-reduction: rinv = 1/(sum of 16 tile partials, fixed order);
// diag softmax value = dexp * rinv. grid 128, block 256.
// ---------------------------------------------------------------------------
__global__ __launch_bounds__(256) void zred_kernel()
{
    const int rid = blockIdx.x * 256 + threadIdx.x;   // 0 .. 32767
    const int pn = rid >> 11;
    const int l = rid & (SEQ - 1);
    float z = 0.f;
#pragma unroll
    for (int s = 0; s < 16; s++)
        z += g_rpart[((size_t)pn * 16 + s) * SEQ + l];
    const float inv = 1.f / z;
    g_rinv[rid] = inv;
    g_diag[rid] = g_dexp[rid] * inv;
}

// ---------------------------------------------------------------------------
// Column sums via symmetric tiles: one read of upper tile T(ti,tj) yields
//   A[c] = sum_r T[r,c]*rinv[ti*128+r]  -> cpart slot ti, block tj
//   B[r] = sum_c T[r,c]*rinv[tj*128+c]  -> cpart slot tj, block ti (ti!=tj)
// grid (136, 8, 2), block 256 (8 warps x 16 rows; lane owns 4 cols).
// Loads batched 8 rows ahead (MLP 8) -- arithmetic order identical to R10.
// ---------------------------------------------------------------------------
__global__ __launch_bounds__(256) void colsum_kernel()
{
    __shared__ float srow[128], scol[128], rowout[128];
    __shared__ float colacc[8][132];

    int ti, tj;
    tile_coords(blockIdx.x, ti, tj);
    const int pn = blockIdx.z * NBATCH + blockIdx.y;
    const float* __restrict__ att = g_att + (size_t)pn * SEQ * SEQ;
    const float* __restrict__ rinv = g_rinv + pn * SEQ;
    const int tid = threadIdx.x;
    const int wid = tid >> 5, lane = tid & 31;

    if (tid < 128) srow[tid] = rinv[ti * 128 + tid];
    else           scol[tid - 128] = rinv[tj * 128 + (tid - 128)];
    __syncthreads();

    const float rv0 = scol[lane * 4 + 0];
    const float rv1 = scol[lane * 4 + 1];
    const float rv2 = scol[lane * 4 + 2];
    const float rv3 = scol[lane * 4 + 3];
    float ca0 = 0.f, ca1 = 0.f, ca2 = 0.f, ca3 = 0.f;

#pragma unroll
    for (int grp = 0; grp < 2; grp++) {
        float4 v[8];
#pragma unroll
        for (int rr = 0; rr < 8; rr++) {
            const int r = wid * 16 + grp * 8 + rr;
            v[rr] = *(const float4*)&att[(size_t)(ti * 128 + r) * SEQ + tj * 128 + lane * 4];
        }
#pragma unroll
        for (int rr = 0; rr < 8; rr++) {
            const int r = wid * 16 + grp * 8 + rr;
            const float w = srow[r];
            ca0 = fmaf(v[rr].x, w, ca0);
            ca1 = fmaf(v[rr].y, w, ca1);
            ca2 = fmaf(v[rr].z, w, ca2);
            ca3 = fmaf(v[rr].w, w, ca3);
            float rs = v[rr].x * rv0 + v[rr].y * rv1 + v[rr].z * rv2 + v[rr].w * rv3;
            rs += __shfl_xor_sync(0xffffffffu, rs, 1);
            rs += __shfl_xor_sync(0xffffffffu, rs, 2);
            rs += __shfl_xor_sync(0xffffffffu, rs, 4);
            rs += __shfl_xor_sync(0xffffffffu, rs, 8);
            rs += __shfl_xor_sync(0xffffffffu, rs, 16);
            if (lane == 0) rowout[r] = rs;
        }
    }
    colacc[wid][lane * 4 + 0] = ca0;
    colacc[wid][lane * 4 + 1] = ca1;
    colacc[wid][lane * 4 + 2] = ca2;
    colacc[wid][lane * 4 + 3] = ca3;
    __syncthreads();

    if (tid < 128) {
        float a = 0.f;
#pragma unroll
        for (int w = 0; w < 8; w++) a += colacc[w][tid];
        g_cpart[((size_t)pn * 16 + ti) * SEQ + tj * 128 + tid] = a;
    } else if (ti != tj) {
        const int r = tid - 128;
        g_cpart[((size_t)pn * 16 + tj) * SEQ + ti * 128 + r] = rowout[r];
    }
}

// ---------------------------------------------------------------------------
// Per (pair,batch): final score (16 fixed-order slots minus diagonal),
// bitonic sort, theta = 1024-th smallest.
// ---------------------------------------------------------------------------
__global__ __launch_bounds__(1024) void select_kernel()
{
    const int pn = blockIdx.x;
    __shared__ float s[2048];
    const int tid = threadIdx.x;
    for (int i = tid; i < SEQ; i += 1024) {
        float v = 0.f;
#pragma unroll
        for (int c = 0; c < 16; c++)
            v += g_cpart[((size_t)pn * 16 + c) * SEQ + i];
        v -= g_diag[pn * SEQ + i];
        g_score[pn * SEQ + i] = v;
        s[i] = v;
    }
    __syncthreads();
    for (int k = 2; k <= 2048; k <<= 1) {
        for (int j = k >> 1; j > 0; j >>= 1) {
            for (int idx = tid; idx < 2048; idx += 1024) {
                int ixj = idx ^ j;
                if (ixj > idx) {
                    bool up = ((idx & k) == 0);
                    float a = s[idx], b = s[ixj];
                    if ((a > b) == up) { s[idx] = b; s[ixj] = a; }
                }
            }
            __syncthreads();
        }
    }
    if (tid == 0) g_theta[pn] = s[1023];   // 1024-th smallest
}

// ---------------------------------------------------------------------------
// Output blend.
// ---------------------------------------------------------------------------
__global__ __launch_bounds__(256) void output_kernel(
    const float* __restrict__ xt, const float* __restrict__ xf, float* __restrict__ out)
{
    const int idx = blockIdx.x * 256 + threadIdx.x;
    const int nl = idx >> 5;
    const int n = nl >> 11;
    const int l = nl & (SEQ - 1);
    const float st = g_score[n * SEQ + l];
    const float sf = g_score[(NBATCH + n) * SEQ + l];
    const bool mt = st <= g_theta[n];
    const bool mf = sf <= g_theta[NBATCH + n];
    const bool mt1 = mt && !mf;
    const bool mf1 = mf && !mt;
    const float4 vt = ((const float4*)xt)[idx];
    const float4 vf = ((const float4*)xf)[idx];
    float4 avg;
    avg.x = 0.5f * (vt.x + vf.x);
    avg.y = 0.5f * (vt.y + vf.y);
    avg.z = 0.5f * (vt.z + vf.z);
    avg.w = 0.5f * (vt.w + vf.w);
    ((float4*)out)[idx] = mt1 ? avg : vt;
    ((float4*)out)[(size_t)NBATCH * SEQ * (DIM / 4) + idx] = mf1 ? avg : vf;
}

extern "C" void kernel_launch(void* const* d_in, const int* in_sizes, int n_in,
                              void* d_out, int out_size)
{
    const float* xt = (const float*)d_in[0];
    const float* xf = (const float*)d_in[1];
    const float* W  = (const float*)d_in[2];
    const float* b  = (const float*)d_in[3];
    float* out = (float*)d_out;

    proj_kernel<<<dim3(128, 2), 256>>>(xt, xf, W, b);
    att_kernel<<<dim3(136, 8, 2), 256>>>();
    zred_kernel<<<128, 256>>>();
    colsum_kernel<<<dim3(136, 8, 2), 256>>>();
    select_kernel<<<16, 1024>>>();
    output_kernel<<<2048, 256>>>(xt, xf, out);
}

// round 17
// speedup vs baseline: 1.0743x; 1.0377x over previous
#include <cuda_runtime.h>
#include <cuda_fp16.h>

#define NBATCH 8
#define SEQ 2048
#define DIM 128
#define NPAIR 2

// Scratch (device globals -- no allocation allowed in kernel_launch)
__device__ __half g_ph[(size_t)NPAIR * NBATCH * SEQ * DIM];        // 8 MB fp16-hi
__device__ __half g_pl[(size_t)NPAIR * NBATCH * SEQ * DIM];        // 8 MB fp16-lo
__device__ float g_att[(size_t)NPAIR * NBATCH * SEQ * SEQ];        // E=exp (full, symmetric)
__device__ float g_rpart[(size_t)NPAIR * NBATCH * 16 * SEQ];       // 2 MB Z partials
__device__ float g_cpart[(size_t)NPAIR * NBATCH * 16 * SEQ];       // 2 MB colsum partials
__device__ float g_dexp[NPAIR * NBATCH * SEQ];                     // diagonal exp
__device__ float g_rinv[NPAIR * NBATCH * SEQ];
__device__ float g_diag[NPAIR * NBATCH * SEQ];                     // diag softmax value
__device__ float g_score[NPAIR * NBATCH * SEQ];
__device__ float g_theta[NPAIR * NBATCH];

// m16n8k16 fp16 MMA, fp32 accum (baseline PTX since sm_75; no 103a feature)
__device__ __forceinline__ void mma_f16(float d[4], const unsigned a[4],
                                        const unsigned b[2]) {
    asm volatile(
        "mma.sync.aligned.m16n8k16.row.col.f32.f16.f16.f32 "
        "{%0,%1,%2,%3}, {%4,%5,%6,%7}, {%8,%9}, {%0,%1,%2,%3};"
        : "+f"(d[0]), "+f"(d[1]), "+f"(d[2]), "+f"(d[3])
        : "r"(a[0]), "r"(a[1]), "r"(a[2]), "r"(a[3]), "r"(b[0]), "r"(b[1]));
}

// Upper-tri tile index -> (ti, tj)
__device__ __forceinline__ void tile_coords(int t, int& ti, int& tj) {
    ti = 0;
    while (t >= 16 - ti) { t -= 16 - ti; ti++; }
    tj = ti + t;
}

// ---------------------------------------------------------------------------
// Projection: P = X @ W^T + b (exact fp32 FMA), then split into fp16 hi/lo.
// R10 version: grid (128, 2), block 256, 128-row tiles.
// ---------------------------------------------------------------------------
__global__ __launch_bounds__(256) void proj_kernel(
    const float* __restrict__ xt, const float* __restrict__ xf,
    const float* __restrict__ W, const float* __restrict__ bias)
{
    __shared__ float As[128][33];
    __shared__ float Bs[128][33];
    const int p = blockIdx.y;
    const float* __restrict__ X = (p == 0) ? xt : xf;
    const int rbase = blockIdx.x * 128;
    const int tid = threadIdx.x;
    const int tx = tid & 15, ty = tid >> 4;
    const int r0 = ty * 8, c0 = tx * 8;
    float acc[8][8];
#pragma unroll
    for (int i = 0; i < 8; i++)
#pragma unroll
        for (int j = 0; j < 8; j++) acc[i][j] = 0.f;

    for (int kk0 = 0; kk0 < DIM; kk0 += 32) {
#pragma unroll
        for (int it = 0; it < 4; it++) {
            int idx4 = it * 256 + tid;
            int r = idx4 >> 3;
            int k4 = (idx4 & 7) * 4;
            float4 v = *(const float4*)(X + (size_t)(rbase + r) * DIM + kk0 + k4);
            As[r][k4 + 0] = v.x; As[r][k4 + 1] = v.y; As[r][k4 + 2] = v.z; As[r][k4 + 3] = v.w;
            float4 w = *(const float4*)(W + (size_t)r * DIM + kk0 + k4);
            Bs[r][k4 + 0] = w.x; Bs[r][k4 + 1] = w.y; Bs[r][k4 + 2] = w.z; Bs[r][k4 + 3] = w.w;
        }
        __syncthreads();
#pragma unroll
        for (int k = 0; k < 32; k++) {
            float a[8], b[8];
#pragma unroll
            for (int j = 0; j < 8; j++) { a[j] = As[r0 + j][k]; b[j] = Bs[c0 + j][k]; }
#pragma unroll
            for (int i = 0; i < 8; i++)
#pragma unroll
                for (int j = 0; j < 8; j++)
                    acc[i][j] = fmaf(a[i], b[j], acc[i][j]);
        }
        __syncthreads();
    }
    float bv[8];
#pragma unroll
    for (int j = 0; j < 8; j++) bv[j] = bias[c0 + j];
    const size_t obase = ((size_t)p * NBATCH * SEQ + rbase) * DIM;
#pragma unroll
    for (int i = 0; i < 8; i++) {
        __half h[8], l[8];
#pragma unroll
        for (int j = 0; j < 8; j++) {
            float v = acc[i][j] + bv[j];
            h[j] = __float2half_rn(v);
            l[j] = __float2half_rn(v - __half2float(h[j]));
        }
        __half* dh = g_ph + obase + (size_t)(r0 + i) * DIM + c0;
        __half* dl = g_pl + obase + (size_t)(r0 + i) * DIM + c0;
#pragma unroll
        for (int j = 0; j < 4; j++) {
            ((__half2*)dh)[j] = __halves2half2(h[2 * j], h[2 * j + 1]);
            ((__half2*)dl)[j] = __halves2half2(l[2 * j], l[2 * j + 1]);
        }
    }
}

// ---------------------------------------------------------------------------
// Attention: E = exp(scale * P P^T) via mma.sync fp16 3x-split
// (hi*hi + hi*lo + lo*hi; dropped lo*lo -- proven margin).
// R10 mainloop EXACTLY (scalar LDS, 3 separate passes, synchronous fills).
// Symmetric: upper-tri tiles computed, BOTH halves stored (R9-stable pattern).
// grid (136, 8, 2), block 256. 8 warps x (32x64) fragments.
// Smem tiles: rows of 16 half2 padded to 20 -> conflict-free fragment loads.
// ---------------------------------------------------------------------------
#define HROW 20                       // half2 (=uint) per row, padded
#define HT_SZ (128 * HROW)            // uints per staged tensor chunk

struct Frag { float v[2][8][4]; };

__device__ __forceinline__ void mac16(const unsigned* __restrict__ A,
                                      const unsigned* __restrict__ B,
                                      Frag& f, int wr, int wc, int lq, int lr)
{
#pragma unroll
    for (int s = 0; s < 2; s++) {          // two k16 steps per 32-k chunk
        const int kb = s * 8;
        unsigned a[2][4], b[8][2];
#pragma unroll
        for (int mt = 0; mt < 2; mt++) {
            const int m = wr * 32 + mt * 16;
            a[mt][0] = A[(m + lq) * HROW + kb + lr];
            a[mt][1] = A[(m + 8 + lq) * HROW + kb + lr];
            a[mt][2] = A[(m + lq) * HROW + kb + 4 + lr];
            a[mt][3] = A[(m + 8 + lq) * HROW + kb + 4 + lr];
        }
#pragma unroll
        for (int nt = 0; nt < 8; nt++) {
            const int n = wc * 64 + nt * 8 + lq;
            b[nt][0] = B[n * HROW + kb + lr];
            b[nt][1] = B[n * HROW + kb + 4 + lr];
        }
#pragma unroll
        for (int mt = 0; mt < 2; mt++)
#pragma unroll
            for (int nt = 0; nt < 8; nt++)
                mma_f16(f.v[mt][nt], a[mt], b[nt]);
    }
}

__global__ __launch_bounds__(256) void att_kernel()
{
    __shared__ unsigned sAh[HT_SZ], sAl[HT_SZ], sBh[HT_SZ], sBl[HT_SZ];

    int ti, tj;
    tile_coords(blockIdx.x, ti, tj);
    const int pn = blockIdx.z * NBATCH + blockIdx.y;
    const size_t pbase = (size_t)pn * SEQ * DIM;
    const __half* __restrict__ Ah = g_ph + pbase + (size_t)ti * 128 * DIM;
    const __half* __restrict__ Al = g_pl + pbase + (size_t)ti * 128 * DIM;
    const __half* __restrict__ Bh = g_ph + pbase + (size_t)tj * 128 * DIM;
    const __half* __restrict__ Bl = g_pl + pbase + (size_t)tj * 128 * DIM;
    float* __restrict__ att = g_att + (size_t)pn * SEQ * SEQ;

    const int tid = threadIdx.x;
    const int wid = tid >> 5, lane = tid & 31;
    const int lq = lane >> 2, lr = lane & 3;
    const int wr = wid & 3, wc = wid >> 2;

    Frag f;
#pragma unroll
    for (int mt = 0; mt < 2; mt++)
#pragma unroll
        for (int nt = 0; nt < 8; nt++)
#pragma unroll
            for (int e = 0; e < 4; e++) f.v[mt][nt][e] = 0.f;

    const int fr = tid >> 1;          // fill row 0..127
    const int fh = tid & 1;           // which 16-half half of the 32-half chunk
    for (int c = 0; c < 4; c++) {
        const int kk0 = c * 32;
        const size_t goff = (size_t)fr * DIM + kk0 + fh * 16;
        const unsigned so = fr * HROW + fh * 8;
        *(uint4*)&sAh[so]     = *(const uint4*)(Ah + goff);
        *(uint4*)&sAh[so + 4] = *(const uint4*)(Ah + goff + 8);
        *(uint4*)&sAl[so]     = *(const uint4*)(Al + goff);
        *(uint4*)&sAl[so + 4] = *(const uint4*)(Al + goff + 8);
        *(uint4*)&sBh[so]     = *(const uint4*)(Bh + goff);
        *(uint4*)&sBh[so + 4] = *(const uint4*)(Bh + goff + 8);
        *(uint4*)&sBl[so]     = *(const uint4*)(Bl + goff);
        *(uint4*)&sBl[so + 4] = *(const uint4*)(Bl + goff + 8);
        __syncthreads();
        mac16(sAh, sBh, f, wr, wc, lq, lr);   // hi*hi
        mac16(sAh, sBl, f, wr, wc, lq, lr);   // hi*lo
        mac16(sAl, sBh, f, wr, wc, lq, lr);   // lo*hi
        __syncthreads();
    }

    // ---- epilogue: E = exp(scale*a), stores + deterministic partial sums ---
    const float scale = 0.088388347648318447f;  // 1/sqrt(128)
    float rp[4] = {0.f, 0.f, 0.f, 0.f};        // row partials (this thread's 4 rows)
    float cp0[8], cp1[8];                       // col partials (even/odd col per nt)
#pragma unroll
    for (int nt = 0; nt < 8; nt++) { cp0[nt] = 0.f; cp1[nt] = 0.f; }

#pragma unroll
    for (int mt = 0; mt < 2; mt++) {
#pragma unroll
        for (int nt = 0; nt < 8; nt++) {
            const int rl = wr * 32 + mt * 16 + lq;          // local row
            const int cl = wc * 64 + nt * 8 + 2 * lr;       // local col
            const float e0 = expf(f.v[mt][nt][0] * scale);
            const float e1 = expf(f.v[mt][nt][1] * scale);
            const float e2 = expf(f.v[mt][nt][2] * scale);
            const float e3 = expf(f.v[mt][nt][3] * scale);
            *(float2*)&att[(size_t)(ti * 128 + rl) * SEQ + tj * 128 + cl] =
                make_float2(e0, e1);
            *(float2*)&att[(size_t)(ti * 128 + rl + 8) * SEQ + tj * 128 + cl] =
                make_float2(e2, e3);
            if (ti != tj) {
                att[(size_t)(tj * 128 + cl) * SEQ + ti * 128 + rl] = e0;
                att[(size_t)(tj * 128 + cl + 1) * SEQ + ti * 128 + rl] = e1;
                att[(size_t)(tj * 128 + cl) * SEQ + ti * 128 + rl + 8] = e2;
                att[(size_t)(tj * 128 + cl + 1) * SEQ + ti * 128 + rl + 8] = e3;
            } else {
                // diagonal exp values
                if (rl == cl)         g_dexp[pn * SEQ + ti * 128 + rl] = e0;
                if (rl == cl + 1)     g_dexp[pn * SEQ + ti * 128 + rl] = e1;
                if (rl + 8 == cl)     g_dexp[pn * SEQ + ti * 128 + rl + 8] = e2;
                if (rl + 8 == cl + 1) g_dexp[pn * SEQ + ti * 128 + rl + 8] = e3;
            }
            rp[mt * 2 + 0] += e0 + e1;
            rp[mt * 2 + 1] += e2 + e3;
            cp0[nt] += e0 + e2;
            cp1[nt] += e1 + e3;
        }
    }

    // row partials: reduce over lr (4 lanes hold different columns, same row)
#pragma unroll
    for (int i = 0; i < 4; i++) {
        rp[i] += __shfl_xor_sync(0xffffffffu, rp[i], 1);
        rp[i] += __shfl_xor_sync(0xffffffffu, rp[i], 2);
    }
    // col partials: reduce over lq (8 lanes hold different rows, same col)
#pragma unroll
    for (int nt = 0; nt < 8; nt++) {
        cp0[nt] += __shfl_xor_sync(0xffffffffu, cp0[nt], 4);
        cp0[nt] += __shfl_xor_sync(0xffffffffu, cp0[nt], 8);
        cp0[nt] += __shfl_xor_sync(0xffffffffu, cp0[nt], 16);
        cp1[nt] += __shfl_xor_sync(0xffffffffu, cp1[nt], 4);
        cp1[nt] += __shfl_xor_sync(0xffffffffu, cp1[nt], 8);
        cp1[nt] += __shfl_xor_sync(0xffffffffu, cp1[nt], 16);
    }

    float* s_row = (float*)sAh;          // [128][2]   (tile smem reuse)
    float* s_col = (float*)sAh + 256;    // [128][4]
    if (lr == 0) {
#pragma unroll
        for (int i = 0; i < 4; i++) {
            int row = wr * 32 + (i >> 1) * 16 + (i & 1) * 8 + lq;
            s_row[row * 2 + wc] = rp[i];
        }
    }
    if (lq == 0) {
#pragma unroll
        for (int nt = 0; nt < 8; nt++) {
            int col = wc * 64 + nt * 8 + 2 * lr;
            s_col[col * 4 + wr] = cp0[nt];
            s_col[(col + 1) * 4 + wr] = cp1[nt];
        }
    }
    __syncthreads();
    if (tid < 128) {
        float z = s_row[tid * 2] + s_row[tid * 2 + 1];
        g_rpart[((size_t)pn * 16 + tj) * SEQ + ti * 128 + tid] = z;
    } else if (ti != tj) {
        int cc = tid - 128;
        float z = s_col[cc * 4] + s_col[cc * 4 + 1] + s_col[cc * 4 + 2] + s_col[cc * 4 + 3];
        g_rpart[((size_t)pn * 16 + ti) * SEQ + tj * 128 + cc] = z;
    }
}

// ---------------------------------------------------------------------------
// Z-reduction: rinv = 1/(sum of 16 tile partials, fixed order);
// diag softmax value = dexp * rinv. grid 128, block 256.
// ---------------------------------------------------------------------------
__global__ __launch_bounds__(256) void zred_kernel()
{
    const int rid = blockIdx.x * 256 + threadIdx.x;   // 0 .. 32767
    const int pn = rid >> 11;
    const int l = rid & (SEQ - 1);
    float z = 0.f;
#pragma unroll
    for (int s = 0; s < 16; s++)
        z += g_rpart[((size_t)pn * 16 + s) * SEQ + l];
    const float inv = 1.f / z;
    g_rinv[rid] = inv;
    g_diag[rid] = g_dexp[rid] * inv;
}

// ---------------------------------------------------------------------------
// Column sums via symmetric tiles: one read of upper tile T(ti,tj) yields
//   A[c] = sum_r T[r,c]*rinv[ti*128+r]  -> cpart slot ti, block tj
//   B[r] = sum_c T[r,c]*rinv[tj*128+c]  -> cpart slot tj, block ti (ti!=tj)
// grid (136, 8, 2), block 256 (8 warps x 16 rows; lane owns 4 cols).
// Loads batched 8 rows ahead (MLP 8) -- arithmetic order identical to R10.
// ---------------------------------------------------------------------------
__global__ __launch_bounds__(256) void colsum_kernel()
{
    __shared__ float srow[128], scol[128], rowout[128];
    __shared__ float colacc[8][132];

    int ti, tj;
    tile_coords(blockIdx.x, ti, tj);
    const int pn = blockIdx.z * NBATCH + blockIdx.y;
    const float* __restrict__ att = g_att + (size_t)pn * SEQ * SEQ;
    const float* __restrict__ rinv = g_rinv + pn * SEQ;
    const int tid = threadIdx.x;
    const int wid = tid >> 5, lane = tid & 31;

    if (tid < 128) srow[tid] = rinv[ti * 128 + tid];
    else           scol[tid - 128] = rinv[tj * 128 + (tid - 128)];
    __syncthreads();

    const float rv0 = scol[lane * 4 + 0];
    const float rv1 = scol[lane * 4 + 1];
    const float rv2 = scol[lane * 4 + 2];
    const float rv3 = scol[lane * 4 + 3];
    float ca0 = 0.f, ca1 = 0.f, ca2 = 0.f, ca3 = 0.f;

#pragma unroll
    for (int grp = 0; grp < 2; grp++) {
        float4 v[8];
#pragma unroll
        for (int rr = 0; rr < 8; rr++) {
            const int r = wid * 16 + grp * 8 + rr;
            v[rr] = *(const float4*)&att[(size_t)(ti * 128 + r) * SEQ + tj * 128 + lane * 4];
        }
#pragma unroll
        for (int rr = 0; rr < 8; rr++) {
            const int r = wid * 16 + grp * 8 + rr;
            const float w = srow[r];
            ca0 = fmaf(v[rr].x, w, ca0);
            ca1 = fmaf(v[rr].y, w, ca1);
            ca2 = fmaf(v[rr].z, w, ca2);
            ca3 = fmaf(v[rr].w, w, ca3);
            float rs = v[rr].x * rv0 + v[rr].y * rv1 + v[rr].z * rv2 + v[rr].w * rv3;
            rs += __shfl_xor_sync(0xffffffffu, rs, 1);
            rs += __shfl_xor_sync(0xffffffffu, rs, 2);
            rs += __shfl_xor_sync(0xffffffffu, rs, 4);
            rs += __shfl_xor_sync(0xffffffffu, rs, 8);
            rs += __shfl_xor_sync(0xffffffffu, rs, 16);
            if (lane == 0) rowout[r] = rs;
        }
    }
    colacc[wid][lane * 4 + 0] = ca0;
    colacc[wid][lane * 4 + 1] = ca1;
    colacc[wid][lane * 4 + 2] = ca2;
    colacc[wid][lane * 4 + 3] = ca3;
    __syncthreads();

    if (tid < 128) {
        float a = 0.f;
#pragma unroll
        for (int w = 0; w < 8; w++) a += colacc[w][tid];
        g_cpart[((size_t)pn * 16 + ti) * SEQ + tj * 128 + tid] = a;
    } else if (ti != tj) {
        const int r = tid - 128;
        g_cpart[((size_t)pn * 16 + tj) * SEQ + ti * 128 + r] = rowout[r];
    }
}

// ---------------------------------------------------------------------------
// Per (pair,batch): final score (16 fixed-order slots minus diagonal), then
// theta = rank-1023 (0-based ascending) element via MSB-first radix select
// on the monotonic unsigned transform of fp32. Bit-identical to sorting:
// returns the exact element value -> identical theta, identical tie behavior.
// grid 16, block 256.
// ---------------------------------------------------------------------------
__global__ __launch_bounds__(256) void select_kernel()
{
    const int pn = blockIdx.x;
    __shared__ unsigned keys[2048];
    __shared__ unsigned sbins[256];
    __shared__ unsigned sprefix;
    __shared__ unsigned srank;
    const int tid = threadIdx.x;

    for (int i = tid; i < SEQ; i += 256) {
        float v = 0.f;
#pragma unroll
        for (int c = 0; c < 16; c++)
            v += g_cpart[((size_t)pn * 16 + c) * SEQ + i];
        v -= g_diag[pn * SEQ + i];
        g_score[pn * SEQ + i] = v;
        unsigned u = __float_as_uint(v);
        keys[i] = (u & 0x80000000u) ? ~u : (u | 0x80000000u);
    }
    if (tid == 0) { sprefix = 0u; srank = 1023u; }
    __syncthreads();

#pragma unroll
    for (int lev = 0; lev < 4; lev++) {
        const int shift = 24 - lev * 8;
        const unsigned himask = (lev == 0) ? 0u : (0xFFFFFFFFu << (shift + 8));
        sbins[tid] = 0u;
        __syncthreads();
        const unsigned pfx = sprefix;
        for (int i = tid; i < SEQ; i += 256) {
            const unsigned u = keys[i];
            if ((u & himask) == pfx)
                atomicAdd(&sbins[(u >> shift) & 0xFFu], 1u);
        }
        __syncthreads();
        if (tid < 32) {
            unsigned part = 0;
#pragma unroll
            for (int j = 0; j < 8; j++) part += sbins[tid * 8 + j];
            unsigned inc = part;
#pragma unroll
            for (int o = 1; o < 32; o <<= 1) {
                unsigned t = __shfl_up_sync(0xffffffffu, inc, o);
                if (tid >= o) inc += t;
            }
            const unsigned excl = inc - part;
            const unsigned r = srank;
            const bool has = (excl <= r) && (r < inc);
            const unsigned m = __ballot_sync(0xffffffffu, has);
            const int sel_lane = __ffs(m) - 1;
            if (tid == sel_lane) {
                unsigned cum = excl;
                int selb = tid * 8;
#pragma unroll
                for (int j = 0; j < 8; j++) {
                    const unsigned c2 = sbins[tid * 8 + j];
                    if (cum + c2 > r) { selb = tid * 8 + j; break; }
                    cum += c2;
                }
                srank = r - cum;
                sprefix = pfx | ((unsigned)selb << shift);
            }
        }
        __syncthreads();
    }

    if (tid == 0) {
        const unsigned u = sprefix;
        const unsigned bits = (u & 0x80000000u) ? (u & 0x7FFFFFFFu) : ~u;
        g_theta[pn] = __uint_as_float(bits);
    }
}

// ---------------------------------------------------------------------------
// Output blend.
// ---------------------------------------------------------------------------
__global__ __launch_bounds__(256) void output_kernel(
    const float* __restrict__ xt, const float* __restrict__ xf, float* __restrict__ out)
{
    const int idx = blockIdx.x * 256 + threadIdx.x;
    const int nl = idx >> 5;
    const int n = nl >> 11;
    const int l = nl & (SEQ - 1);
    const float st = g_score[n * SEQ + l];
    const float sf = g_score[(NBATCH + n) * SEQ + l];
    const bool mt = st <= g_theta[n];
    const bool mf = sf <= g_theta[NBATCH + n];
    const bool mt1 = mt && !mf;
    const bool mf1 = mf && !mt;
    const float4 vt = ((const float4*)xt)[idx];
    const float4 vf = ((const float4*)xf)[idx];
    float4 avg;
    avg.x = 0.5f * (vt.x + vf.x);
    avg.y = 0.5f * (vt.y + vf.y);
    avg.z = 0.5f * (vt.z + vf.z);
    avg.w = 0.5f * (vt.w + vf.w);
    ((float4*)out)[idx] = mt1 ? avg : vt;
    ((float4*)out)[(size_t)NBATCH * SEQ * (DIM / 4) + idx] = mf1 ? avg : vf;
}

extern "C" void kernel_launch(void* const* d_in, const int* in_sizes, int n_in,
                              void* d_out, int out_size)
{
    const float* xt = (const float*)d_in[0];
    const float* xf = (const float*)d_in[1];
    const float* W  = (const float*)d_in[2];
    const float* b  = (const float*)d_in[3];
    float* out = (float*)d_out;

    proj_kernel<<<dim3(128, 2), 256>>>(xt, xf, W, b);
    att_kernel<<<dim3(136, 8, 2), 256>>>();
    zred_kernel<<<128, 256>>>();
    colsum_kernel<<<dim3(136, 8, 2), 256>>>();
    select_kernel<<<16, 256>>>();
    output_kernel<<<2048, 256>>>(xt, xf, out);
}